// round 12
// baseline (speedup 1.0000x reference)
#include <cuda_runtime.h>
#include <cuda_bf16.h>
#include <cstdint>

// GAT fused kernel, GB300 sm_103a.
// B=8, N=512, T=128, DIN=DOUT=128, H=8, HD=16.
//
// Factorization (exactly equivalent to reference):
//   softmax-effective score[b,t,h,n] = h[b,n,t,:] . wtil_h   (row-constant terms cancel)
//     wtil_h[k] = sum_d W1[k, h*16+d] * Wa[16+d]
//   e = mask * exp(score);  w = e * rv,  rv = 1/(adj==0 ? 1e9 : adj)
//   Z_h = sum_n e;  S_h = (sum_n w)/Z_h;  g_h = (sum_n w*h_n)/Z_h
//   agg[h*16+d] = g_h . W1[:, h*16+d] + S_h * b1[h*16+d]
//   th = h0 @ W1 + b1
//   out = agg @ W2[:128] + th @ W2[128:] + b2
//
// mask/adj folded into enc = (mask ? +1/adj' : -1/adj'), stored in the pad
// float (col 128) of each staged h row.
//
// Phase A is a blocked dot product: thread (rgA, seg) covers rows
// {rgA, rgA+32} x cols [seg*16,seg*16+16) x all 8 heads, partials reduced
// across the seg-octet with a 3-round shfl butterfly (cuts phase-A LDS
// lane-bytes 2.4x; the kernel was L1-crossbar bound at 84%).

#define Bv 8
#define Nv 512
#define Tv 128
#define Dv 128
#define Hv 8
#define CH 64
#define NCHUNK 8
#define ROWP 132   // padded row pitch (floats); col 128 carries enc

typedef unsigned long long ull;

// ---------------- scratch ----------------
__device__ float G_scr[Bv * Tv * Hv * Dv];
__device__ float S_scr[Bv * Tv * Hv];

// ---------------- f32x2 helpers ----------------
__device__ __forceinline__ ull f2fma(ull a, ull b, ull c) {
    ull d; asm("fma.rn.f32x2 %0,%1,%2,%3;" : "=l"(d) : "l"(a), "l"(b), "l"(c)); return d;
}
__device__ __forceinline__ ull f2add(ull a, ull b) {
    ull d; asm("add.rn.f32x2 %0,%1,%2;" : "=l"(d) : "l"(a), "l"(b)); return d;
}
__device__ __forceinline__ ull f2mul(ull a, ull b) {
    ull d; asm("mul.rn.f32x2 %0,%1,%2;" : "=l"(d) : "l"(a), "l"(b)); return d;
}
__device__ __forceinline__ ull packrep(float x) {
    ull d; asm("mov.b64 %0,{%1,%1};" : "=l"(d) : "f"(x)); return d;
}
__device__ __forceinline__ ull pack2(float x, float y) {
    ull d; asm("mov.b64 %0,{%1,%2};" : "=l"(d) : "f"(x), "f"(y)); return d;
}
__device__ __forceinline__ float2 unpk(ull a) {
    float2 r; asm("mov.b64 {%0,%1},%2;" : "=f"(r.x), "=f"(r.y) : "l"(a)); return r;
}

// ---------------- main: stream h, attention stats ----------------
// dynamic smem layout (floats):
//   hbuf : 2 * CH * ROWP = 16896  @ 0
//   wts  : 8 * ROWP      = 1056   @ 16896
//   ws   : CH * 8        = 512    @ 17952
//   zred : 64                     @ 18464
//   wred : 64                     @ 18528
//   invZ : 8                      @ 18592
//   was  : 16                     @ 18600
#define MAIN_SMEM_FLOATS 18616

__global__ __launch_bounds__(256, 2) void gat_main(const float* __restrict__ hin,
                                                   const float* __restrict__ adj,
                                                   const float* __restrict__ mask,
                                                   const float* __restrict__ W1,
                                                   const float* __restrict__ Wa) {
    extern __shared__ __align__(16) float sm[];
    float* hbuf = sm;
    float* wts  = sm + 16896;
    float* ws   = sm + 17952;
    float* zred = sm + 18464;
    float* wred = sm + 18528;
    float* invZ = sm + 18592;
    float* was  = sm + 18600;

    const int bt = blockIdx.x;
    const int b = bt >> 7;
    const int t = bt & 127;
    const int tid = threadIdx.x;

    // per-thread encoded mask/adj values (rows n=tid and n=tid+256)
    float enc0, enc1;

    // ---- async chunk loader (pure cp.async + enc pad store) ----
    auto issue = [&](int c) {
        const int buf = c & 1;
        const float* base = hin + (((size_t)(b * Nv + c * CH)) * Tv + t) * Dv;
        float* hb = hbuf + buf * (CH * ROWP);
        #pragma unroll
        for (int i = 0; i < 8; i++) {
            int lin = i * 256 + tid;
            int r = lin >> 5;
            int j = lin & 31;
            const float* gp = base + (size_t)r * (Tv * Dv) + j * 4;
            unsigned sa = (unsigned)__cvta_generic_to_shared(&hb[r * ROWP + j * 4]);
            asm volatile("cp.async.cg.shared.global [%0], [%1], 16;" :: "r"(sa), "l"(gp));
        }
        if ((tid >> 6) == c)     hb[(tid & 63) * ROWP + 128] = enc0;
        if ((tid >> 6) == c - 4) hb[(tid & 63) * ROWP + 128] = enc1;
        asm volatile("cp.async.commit_group;");
    };

    // ---- one-time prologue: mask/adj -> enc regs (overlaps chunk-0 DMA) ----
    {
        const float* mrow = mask + (size_t)b * Nv * Tv + t;
        const float* arow = adj + (size_t)(b * Tv + t) * Nv;
        float m0 = mrow[(size_t)tid * Tv];
        float m1 = mrow[(size_t)(tid + 256) * Tv];
        float a0 = arow[tid];
        float a1 = arow[tid + 256];
        a0 = (a0 == 0.f) ? 1e9f : a0;
        a1 = (a1 == 0.f) ? 1e9f : a1;
        enc0 = (m0 > 0.5f ? 1.f : -1.f) * (1.0f / a0);
        enc1 = (m1 > 0.5f ? 1.f : -1.f) * (1.0f / a1);
    }

    issue(0);

    // ---- compute wtil into smem (overlaps chunk-0 DMA) ----
    if (tid < 16) was[tid] = Wa[16 + tid];
    __syncthreads();
    for (int idx = tid; idx < 1024; idx += 256) {
        int hh = idx >> 7, k = idx & 127;
        const float* w1p = W1 + k * 128 + hh * 16;
        float a = 0.f;
        #pragma unroll
        for (int d = 0; d < 16; d++)
            a = fmaf(w1p[d], was[d], a);
        wts[hh * ROWP + k] = a;
    }

    // phase A identity: thread = (rows rgA & rgA+32, col segment seg)
    const int rgA = tid >> 3;
    const int seg = tid & 7;
    // phase B identity: thread = (rowgroup rg = warp, col-quad kc)
    const int rg = tid >> 5;
    const int kc = tid & 31;

    ull acc[16];
    #pragma unroll
    for (int q = 0; q < 16; q++) acc[q] = 0ull;
    float zsum = 0.f, wsum = 0.f;

    #pragma unroll 1
    for (int c = 0; c < NCHUNK; c++) {
        if (c + 1 < NCHUNK) {
            issue(c + 1);
            asm volatile("cp.async.wait_group 1;");
        } else {
            asm volatile("cp.async.wait_group 0;");
        }
        __syncthreads();
        const int buf = c & 1;
        float* hb = hbuf + buf * (CH * ROWP);

        // ---- phase A: blocked scores + shfl-butterfly reduction ----
        {
            const ulonglong2* xr0 = (const ulonglong2*)&hb[rgA * ROWP + seg * 16];
            const ulonglong2* xr1 = (const ulonglong2*)&hb[(rgA + 32) * ROWP + seg * 16];
            ulonglong2 xa0 = xr0[0], xa1 = xr0[1], xa2 = xr0[2], xa3 = xr0[3];
            ulonglong2 xb0 = xr1[0], xb1 = xr1[1], xb2 = xr1[2], xb3 = xr1[3];

            ull sc[8];
            #pragma unroll
            for (int h = 0; h < 8; h++) {
                const ulonglong2* wr = (const ulonglong2*)&wts[h * ROWP + seg * 16];
                ulonglong2 w0 = wr[0], w1 = wr[1];
                ull p0 = f2mul(xa0.x, w0.x);
                ull p1 = f2mul(xb0.x, w0.x);
                p0 = f2fma(xa0.y, w0.y, p0);  p1 = f2fma(xb0.y, w0.y, p1);
                p0 = f2fma(xa1.x, w1.x, p0);  p1 = f2fma(xb1.x, w1.x, p1);
                p0 = f2fma(xa1.y, w1.y, p0);  p1 = f2fma(xb1.y, w1.y, p1);
                ulonglong2 w2 = wr[2], w3 = wr[3];
                p0 = f2fma(xa2.x, w2.x, p0);  p1 = f2fma(xb2.x, w2.x, p1);
                p0 = f2fma(xa2.y, w2.y, p0);  p1 = f2fma(xb2.y, w2.y, p1);
                p0 = f2fma(xa3.x, w3.x, p0);  p1 = f2fma(xb3.x, w3.x, p1);
                p0 = f2fma(xa3.y, w3.y, p0);  p1 = f2fma(xb3.y, w3.y, p1);
                float2 q0 = unpk(p0);
                float2 q1 = unpk(p1);
                sc[h] = pack2(q0.x + q0.y, q1.x + q1.y);
            }
            // butterfly over the 8-lane seg-octet (bits 0..2 of lane id)
            #pragma unroll
            for (int d = 1; d < 8; d <<= 1) {
                #pragma unroll
                for (int h = 0; h < 8; h++)
                    sc[h] = f2add(sc[h], __shfl_xor_sync(0xffffffffu, sc[h], d));
            }
            // lane seg owns head seg
            ull mysc = sc[0];
            #pragma unroll
            for (int h = 1; h < 8; h++)
                if (seg == h) mysc = sc[h];
            float2 s = unpk(mysc);
            float en0 = hb[rgA * ROWP + 128];
            float en1 = hb[(rgA + 32) * ROWP + 128];
            float e0 = (en0 > 0.f) ? __expf(s.x) : 0.f;
            float e1 = (en1 > 0.f) ? __expf(s.y) : 0.f;
            float w0 = e0 * fabsf(en0);
            float w1 = e1 * fabsf(en1);
            ws[rgA * 8 + seg] = w0;
            ws[(rgA + 32) * 8 + seg] = w1;
            zsum += e0 + e1;
            wsum += w0 + w1;
        }
        __syncthreads();

        // ---- phase B: register-accumulated rank-64 update ----
        {
            #pragma unroll
            for (int i = 0; i < 8; i++) {
                int r = rg * 8 + i;
                float4 wa = *(const float4*)&ws[r * 8];
                float4 wb = *(const float4*)&ws[r * 8 + 4];
                ulonglong2 x = *(const ulonglong2*)&hb[r * ROWP + kc * 4];
                ull w0 = packrep(wa.x), w1 = packrep(wa.y);
                ull w2 = packrep(wa.z), w3 = packrep(wa.w);
                ull w4 = packrep(wb.x), w5 = packrep(wb.y);
                ull w6 = packrep(wb.z), w7 = packrep(wb.w);
                acc[0]  = f2fma(w0, x.x, acc[0]);  acc[1]  = f2fma(w0, x.y, acc[1]);
                acc[2]  = f2fma(w1, x.x, acc[2]);  acc[3]  = f2fma(w1, x.y, acc[3]);
                acc[4]  = f2fma(w2, x.x, acc[4]);  acc[5]  = f2fma(w2, x.y, acc[5]);
                acc[6]  = f2fma(w3, x.x, acc[6]);  acc[7]  = f2fma(w3, x.y, acc[7]);
                acc[8]  = f2fma(w4, x.x, acc[8]);  acc[9]  = f2fma(w4, x.y, acc[9]);
                acc[10] = f2fma(w5, x.x, acc[10]); acc[11] = f2fma(w5, x.y, acc[11]);
                acc[12] = f2fma(w6, x.x, acc[12]); acc[13] = f2fma(w6, x.y, acc[13]);
                acc[14] = f2fma(w7, x.x, acc[14]); acc[15] = f2fma(w7, x.y, acc[15]);
            }
        }
        __syncthreads();
    }

    // ---- reduce Z, Sw per head (head = tid&7, rows split over tid>>3) ----
    zsum += __shfl_xor_sync(0xffffffffu, zsum, 8);
    zsum += __shfl_xor_sync(0xffffffffu, zsum, 16);
    wsum += __shfl_xor_sync(0xffffffffu, wsum, 8);
    wsum += __shfl_xor_sync(0xffffffffu, wsum, 16);
    const int warp = tid >> 5, lane = tid & 31;
    if (lane < 8) { zred[warp * 8 + lane] = zsum; wred[warp * 8 + lane] = wsum; }
    __syncthreads();
    if (tid < 8) {
        float Z = 0.f, W = 0.f;
        #pragma unroll
        for (int i = 0; i < 8; i++) { Z += zred[i * 8 + tid]; W += wred[i * 8 + tid]; }
        float iZ = 1.0f / Z;
        invZ[tid] = iZ;
        S_scr[bt * 8 + tid] = W * iZ;
    }

    // ---- dump per-thread G partials into (reused) hbuf, tree-reduce, write ----
    {
        ull* red = (ull*)hbuf;   // 256 threads * 16 ull = 32 KB
        ulonglong2* my = (ulonglong2*)(red + (size_t)tid * 16);
        #pragma unroll
        for (int q = 0; q < 8; q++)
            my[q] = make_ulonglong2(acc[2 * q], acc[2 * q + 1]);
    }
    __syncthreads();
    {
        const ull* red = (const ull*)hbuf;
        #pragma unroll
        for (int o = 0; o < 2; o++) {
            int oi = tid * 2 + o;          // 0..511
            int hh  = oi >> 6;
            int kc2 = oi & 63;
            int kcc = kc2 >> 1, p = kc2 & 1;
            ull s = red[((size_t)kcc) * 16 + hh * 2 + p];
            #pragma unroll
            for (int g = 1; g < 8; g++)
                s = f2add(s, red[((size_t)(g * 32 + kcc)) * 16 + hh * 2 + p]);
            s = f2mul(s, packrep(invZ[hh]));
            ((ull*)G_scr)[(size_t)bt * 512 + hh * 64 + kc2] = s;
        }
    }
}

// ---------------- epilogue: 1024 lightweight blocks ----------------
// block = one (b,t), 128 threads. Weights via __ldg (L1/L2 resident).
__global__ __launch_bounds__(128) void gat_epi(const float* __restrict__ hin,
                                               const float* __restrict__ W1,
                                               const float* __restrict__ W2,
                                               const float* __restrict__ b1,
                                               const float* __restrict__ b2,
                                               float* __restrict__ out) {
    __shared__ __align__(16) float gs[8 * 132];
    __shared__ __align__(16) float h0s[128];
    __shared__ __align__(16) float aggs[128];
    __shared__ __align__(16) float ths[128];
    __shared__ float Ss[8];

    const int bt = blockIdx.x;
    const int b = bt >> 7;
    const int t = bt & 127;
    const int tid = threadIdx.x;

    #pragma unroll
    for (int i = 0; i < 8; i++) {
        int idx = i * 128 + tid;
        gs[(idx >> 7) * 132 + (idx & 127)] = G_scr[(size_t)bt * 1024 + idx];
    }
    h0s[tid] = hin[((size_t)(b * Nv) * Tv + t) * Dv + tid];
    if (tid < 8) Ss[tid] = S_scr[bt * 8 + tid];
    __syncthreads();

    // stage 1: thread j: agg[j] = g_h.W1[:,j] + S_h*b1[j];  th[j] = h0.W1[:,j] + b1[j]
    {
        const int j = tid;
        const int hh = j >> 4;
        float bj = __ldg(&b1[j]);
        float agg = Ss[hh] * bj;
        float th = bj;
        const float* gp = &gs[hh * 132];
        #pragma unroll 8
        for (int m = 0; m < 128; m++) {
            float w = __ldg(&W1[m * 128 + j]);
            agg = fmaf(gp[m], w, agg);
            th  = fmaf(h0s[m], w, th);
        }
        aggs[j] = agg;
        ths[j] = th;
    }
    __syncthreads();

    // stage 2: out[k] = agg @ W2a + th @ W2b + b2
    {
        const int k = tid;
        float o = __ldg(&b2[k]);
        #pragma unroll 8
        for (int j = 0; j < 128; j++) {
            o = fmaf(aggs[j], __ldg(&W2[j * 128 + k]), o);
            o = fmaf(ths[j],  __ldg(&W2[(128 + j) * 128 + k]), o);
        }
        out[(size_t)bt * 128 + k] = o;
    }
}

// third kernel: keeps ncu's fixed capture slot on gat_main
__global__ void gat_nop() {}

// ---------------- launch ----------------
extern "C" void kernel_launch(void* const* d_in, const int* in_sizes, int n_in,
                              void* d_out, int out_size) {
    const float* h    = (const float*)d_in[0];
    const float* adj  = (const float*)d_in[1];
    const float* mask = (const float*)d_in[2];
    const float* W1   = (const float*)d_in[3];
    const float* b1   = (const float*)d_in[4];
    const float* Wa   = (const float*)d_in[5];
    // d_in[6] = ba (cancels in softmax; unused)
    const float* W2   = (const float*)d_in[7];
    const float* b2   = (const float*)d_in[8];
    float* out = (float*)d_out;

    cudaFuncSetAttribute(gat_main, cudaFuncAttributeMaxDynamicSharedMemorySize,
                         MAIN_SMEM_FLOATS * (int)sizeof(float));

    gat_main<<<Bv * Tv, 256, MAIN_SMEM_FLOATS * sizeof(float)>>>(h, adj, mask, W1, Wa);
    gat_epi<<<Bv * Tv, 128>>>(h, W1, W2, b1, b2, out);
    gat_nop<<<1, 32>>>();
}

// round 13
// speedup vs baseline: 1.5156x; 1.5156x over previous
#include <cuda_runtime.h>
#include <cuda_bf16.h>
#include <cstdint>

// GAT fused kernel, GB300 sm_103a.
// B=8, N=512, T=128, DIN=DOUT=128, H=8, HD=16.
//
// Factorization (exactly equivalent to reference):
//   softmax-effective score[b,t,h,n] = h[b,n,t,:] . wtil_h   (row-constant terms cancel)
//     wtil_h[k] = sum_d W1[k, h*16+d] * Wa[16+d]
//   e = mask * exp(score);  w = e * rv,  rv = 1/(adj==0 ? 1e9 : adj)
//   Z_h = sum_n e;  S_h = (sum_n w)/Z_h;  g_h = (sum_n w*h_n)/Z_h
//   agg[h*16+d] = g_h . W1[:, h*16+d] + S_h * b1[h*16+d]
//   th = h0 @ W1 + b1
//   out = agg @ W2[:128] + th @ W2[128:] + b2
//
// Single fused pass per chunk: warp rg handles rows rg*8..rg*8+7; each lane
// (kc) holds cols kc*4..kc*4+3. Scores are computed from the SAME register
// data as the G-update (wtil column-slice lives in registers), reduced
// across lanes with an ownership-halving shfl butterfly. No phase-A smem
// reads at all (the R11/R12 kernels were smem-lane-byte bound at 84-89% L1).

#define Bv 8
#define Nv 512
#define Tv 128
#define Dv 128
#define Hv 8
#define CH 64
#define NCHUNK 8
#define ROWP 132   // padded row pitch (floats); col 128 carries enc

typedef unsigned long long ull;

// ---------------- scratch ----------------
__device__ float G_scr[Bv * Tv * Hv * Dv];
__device__ float S_scr[Bv * Tv * Hv];

// ---------------- f32x2 helpers ----------------
__device__ __forceinline__ ull f2fma(ull a, ull b, ull c) {
    ull d; asm("fma.rn.f32x2 %0,%1,%2,%3;" : "=l"(d) : "l"(a), "l"(b), "l"(c)); return d;
}
__device__ __forceinline__ ull f2add(ull a, ull b) {
    ull d; asm("add.rn.f32x2 %0,%1,%2;" : "=l"(d) : "l"(a), "l"(b)); return d;
}
__device__ __forceinline__ ull f2mul(ull a, ull b) {
    ull d; asm("mul.rn.f32x2 %0,%1,%2;" : "=l"(d) : "l"(a), "l"(b)); return d;
}
__device__ __forceinline__ ull packrep(float x) {
    ull d; asm("mov.b64 %0,{%1,%1};" : "=l"(d) : "f"(x)); return d;
}
__device__ __forceinline__ ull pack2(float x, float y) {
    ull d; asm("mov.b64 %0,{%1,%2};" : "=l"(d) : "f"(x), "f"(y)); return d;
}
__device__ __forceinline__ float2 unpk(ull a) {
    float2 r; asm("mov.b64 {%0,%1},%2;" : "=f"(r.x), "=f"(r.y) : "l"(a)); return r;
}

// ---------------- main: stream h, attention stats ----------------
// dynamic smem layout (floats):
//   hbuf : 2 * CH * ROWP = 16896  @ 0
//   wts  : 8 * ROWP      = 1056   @ 16896
//   zred : 64                     @ 17952
//   wred : 64                     @ 18016
//   invZ : 8                      @ 18080
//   was  : 16                     @ 18088
#define MAIN_SMEM_FLOATS 18104

__global__ __launch_bounds__(256, 2) void gat_main(const float* __restrict__ hin,
                                                   const float* __restrict__ adj,
                                                   const float* __restrict__ mask,
                                                   const float* __restrict__ W1,
                                                   const float* __restrict__ Wa) {
    extern __shared__ __align__(16) float sm[];
    float* hbuf = sm;
    float* wts  = sm + 16896;
    float* zred = sm + 17952;
    float* wred = sm + 18016;
    float* invZ = sm + 18080;
    float* was  = sm + 18088;

    const int bt = blockIdx.x;
    const int b = bt >> 7;
    const int t = bt & 127;
    const int tid = threadIdx.x;
    const int warp = tid >> 5;
    const int lane = tid & 31;

    // per-thread encoded mask/adj values (rows n=tid and n=tid+256)
    float enc0, enc1;

    // ---- async chunk loader (pure cp.async + enc pad store) ----
    auto issue = [&](int c) {
        const int buf = c & 1;
        const float* base = hin + (((size_t)(b * Nv + c * CH)) * Tv + t) * Dv;
        float* hb = hbuf + buf * (CH * ROWP);
        #pragma unroll
        for (int i = 0; i < 8; i++) {
            int lin = i * 256 + tid;
            int r = lin >> 5;
            int j = lin & 31;
            const float* gp = base + (size_t)r * (Tv * Dv) + j * 4;
            unsigned sa = (unsigned)__cvta_generic_to_shared(&hb[r * ROWP + j * 4]);
            asm volatile("cp.async.cg.shared.global [%0], [%1], 16;" :: "r"(sa), "l"(gp));
        }
        if ((tid >> 6) == c)     hb[(tid & 63) * ROWP + 128] = enc0;
        if ((tid >> 6) == c - 4) hb[(tid & 63) * ROWP + 128] = enc1;
        asm volatile("cp.async.commit_group;");
    };

    // ---- one-time prologue: mask/adj -> enc regs (overlaps chunk-0 DMA) ----
    {
        const float* mrow = mask + (size_t)b * Nv * Tv + t;
        const float* arow = adj + (size_t)(b * Tv + t) * Nv;
        float m0 = mrow[(size_t)tid * Tv];
        float m1 = mrow[(size_t)(tid + 256) * Tv];
        float a0 = arow[tid];
        float a1 = arow[tid + 256];
        a0 = (a0 == 0.f) ? 1e9f : a0;
        a1 = (a1 == 0.f) ? 1e9f : a1;
        enc0 = (m0 > 0.5f ? 1.f : -1.f) * (1.0f / a0);
        enc1 = (m1 > 0.5f ? 1.f : -1.f) * (1.0f / a1);
    }

    issue(0);

    // ---- compute wtil into smem (overlaps chunk-0 DMA) ----
    if (tid < 16) was[tid] = Wa[16 + tid];
    __syncthreads();
    for (int idx = tid; idx < 1024; idx += 256) {
        int hh = idx >> 7, k = idx & 127;
        const float* w1p = W1 + k * 128 + hh * 16;
        float a = 0.f;
        #pragma unroll
        for (int d = 0; d < 16; d++)
            a = fmaf(w1p[d], was[d], a);
        wts[hh * ROWP + k] = a;
    }
    __syncthreads();

    // thread identity: warp rg covers rows rg*8..rg*8+7, lane kc covers
    // cols kc*4..kc*4+3 (all 8 heads).
    const int rg = warp;
    const int kc = lane;

    // wtil column-slice in registers: wreg[2h+p] = wtil[h][kc*4+2p .. +1]
    ull wreg[16];
    #pragma unroll
    for (int h = 0; h < 8; h++) {
        wreg[2 * h]     = *(const ull*)&wts[h * ROWP + kc * 4];
        wreg[2 * h + 1] = *(const ull*)&wts[h * ROWP + kc * 4 + 2];
    }

    ull acc[16];
    #pragma unroll
    for (int q = 0; q < 16; q++) acc[q] = 0ull;
    float zsum = 0.f, wsum = 0.f;

    const bool b16 = (lane & 16) != 0;
    const bool b8  = (lane & 8) != 0;
    const bool b4  = (lane & 4) != 0;

    #pragma unroll 1
    for (int c = 0; c < NCHUNK; c++) {
        if (c + 1 < NCHUNK) {
            issue(c + 1);
            asm volatile("cp.async.wait_group 1;");
        } else {
            asm volatile("cp.async.wait_group 0;");
        }
        __syncthreads();
        const int buf = c & 1;
        const float* hb = hbuf + buf * (CH * ROWP);

        #pragma unroll
        for (int pr = 0; pr < 4; pr++) {
            const int r = rg * 8 + pr * 2;
            ulonglong2 xa = *(const ulonglong2*)&hb[r * ROWP + kc * 4];
            ulonglong2 xb = *(const ulonglong2*)&hb[(r + 1) * ROWP + kc * 4];

            // score partials: sp[h] = (row r partial, row r+1 partial)
            ull sp[8];
            #pragma unroll
            for (int h = 0; h < 8; h++) {
                ull pa = f2fma(xa.y, wreg[2 * h + 1], f2mul(xa.x, wreg[2 * h]));
                ull pb = f2fma(xb.y, wreg[2 * h + 1], f2mul(xb.x, wreg[2 * h]));
                float2 qa = unpk(pa);
                float2 qb = unpk(pb);
                sp[h] = pack2(qa.x + qa.y, qb.x + qb.y);
            }

            // ownership-halving butterfly over 32 lanes:
            // lane l ends with the full score (f32x2, rows r/r+1) of head (l>>2)&7
            ull v4[4];
            #pragma unroll
            for (int j = 0; j < 4; j++) {
                ull keep = b16 ? sp[j + 4] : sp[j];
                ull send = b16 ? sp[j] : sp[j + 4];
                v4[j] = f2add(keep, __shfl_xor_sync(0xffffffffu, send, 16));
            }
            ull v2[2];
            #pragma unroll
            for (int j = 0; j < 2; j++) {
                ull keep = b8 ? v4[j + 2] : v4[j];
                ull send = b8 ? v4[j] : v4[j + 2];
                v2[j] = f2add(keep, __shfl_xor_sync(0xffffffffu, send, 8));
            }
            ull v1;
            {
                ull keep = b4 ? v2[1] : v2[0];
                ull send = b4 ? v2[0] : v2[1];
                v1 = f2add(keep, __shfl_xor_sync(0xffffffffu, send, 4));
            }
            v1 = f2add(v1, __shfl_xor_sync(0xffffffffu, v1, 2));
            v1 = f2add(v1, __shfl_xor_sync(0xffffffffu, v1, 1));

            // e / w for the owned head
            float en0 = hb[r * ROWP + 128];
            float en1 = hb[(r + 1) * ROWP + 128];
            float2 s = unpk(v1);
            float e0 = (en0 > 0.f) ? __expf(s.x) : 0.f;
            float e1 = (en1 > 0.f) ? __expf(s.y) : 0.f;
            float w0 = e0 * fabsf(en0);
            float w1 = e1 * fabsf(en1);
            zsum += e0 + e1;
            wsum += w0 + w1;

            // gather all heads' w and update G
            ull wp = pack2(w0, w1);
            #pragma unroll
            for (int h = 0; h < 8; h++) {
                ull wh = __shfl_sync(0xffffffffu, wp, h * 4);
                float2 wf = unpk(wh);
                ull wr0 = packrep(wf.x);
                ull wr1 = packrep(wf.y);
                acc[2 * h]     = f2fma(wr0, xa.x, acc[2 * h]);
                acc[2 * h]     = f2fma(wr1, xb.x, acc[2 * h]);
                acc[2 * h + 1] = f2fma(wr0, xa.y, acc[2 * h + 1]);
                acc[2 * h + 1] = f2fma(wr1, xb.y, acc[2 * h + 1]);
            }
        }
    }

    // ---- per-warp Z/W partials: owner lanes (l&3)==0 hold head (l>>2) ----
    if ((lane & 3) == 0) {
        zred[warp * 8 + (lane >> 2)] = zsum;
        wred[warp * 8 + (lane >> 2)] = wsum;
    }
    __syncthreads();
    if (tid < 8) {
        float Z = 0.f, W = 0.f;
        #pragma unroll
        for (int i = 0; i < 8; i++) { Z += zred[i * 8 + tid]; W += wred[i * 8 + tid]; }
        float iZ = 1.0f / Z;
        invZ[tid] = iZ;
        S_scr[bt * 8 + tid] = W * iZ;
    }

    // ---- dump per-thread G partials into (reused) hbuf, tree-reduce, write ----
    {
        ull* red = (ull*)hbuf;   // 256 threads * 16 ull = 32 KB
        ulonglong2* my = (ulonglong2*)(red + (size_t)tid * 16);
        #pragma unroll
        for (int q = 0; q < 8; q++)
            my[q] = make_ulonglong2(acc[2 * q], acc[2 * q + 1]);
    }
    __syncthreads();
    {
        const ull* red = (const ull*)hbuf;
        #pragma unroll
        for (int o = 0; o < 2; o++) {
            int oi = tid * 2 + o;          // 0..511
            int hh  = oi >> 6;
            int kc2 = oi & 63;
            int kcc = kc2 >> 1, p = kc2 & 1;
            ull s = red[((size_t)kcc) * 16 + hh * 2 + p];
            #pragma unroll
            for (int g = 1; g < 8; g++)
                s = f2add(s, red[((size_t)(g * 32 + kcc)) * 16 + hh * 2 + p]);
            s = f2mul(s, packrep(invZ[hh]));
            ((ull*)G_scr)[(size_t)bt * 512 + hh * 64 + kc2] = s;
        }
    }
}

// ---------------- epilogue: 1024 lightweight blocks ----------------
// block = one (b,t), 128 threads. Weights via __ldg (L1/L2 resident).
__global__ __launch_bounds__(128) void gat_epi(const float* __restrict__ hin,
                                               const float* __restrict__ W1,
                                               const float* __restrict__ W2,
                                               const float* __restrict__ b1,
                                               const float* __restrict__ b2,
                                               float* __restrict__ out) {
    __shared__ __align__(16) float gs[8 * 132];
    __shared__ __align__(16) float h0s[128];
    __shared__ __align__(16) float aggs[128];
    __shared__ __align__(16) float ths[128];
    __shared__ float Ss[8];

    const int bt = blockIdx.x;
    const int b = bt >> 7;
    const int t = bt & 127;
    const int tid = threadIdx.x;

    #pragma unroll
    for (int i = 0; i < 8; i++) {
        int idx = i * 128 + tid;
        gs[(idx >> 7) * 132 + (idx & 127)] = G_scr[(size_t)bt * 1024 + idx];
    }
    h0s[tid] = hin[((size_t)(b * Nv) * Tv + t) * Dv + tid];
    if (tid < 8) Ss[tid] = S_scr[bt * 8 + tid];
    __syncthreads();

    // stage 1: thread j: agg[j] = g_h.W1[:,j] + S_h*b1[j];  th[j] = h0.W1[:,j] + b1[j]
    {
        const int j = tid;
        const int hh = j >> 4;
        float bj = __ldg(&b1[j]);
        float agg = Ss[hh] * bj;
        float th = bj;
        const float* gp = &gs[hh * 132];
        #pragma unroll 8
        for (int m = 0; m < 128; m++) {
            float w = __ldg(&W1[m * 128 + j]);
            agg = fmaf(gp[m], w, agg);
            th  = fmaf(h0s[m], w, th);
        }
        aggs[j] = agg;
        ths[j] = th;
    }
    __syncthreads();

    // stage 2: out[k] = agg @ W2a + th @ W2b + b2
    {
        const int k = tid;
        float o = __ldg(&b2[k]);
        #pragma unroll 8
        for (int j = 0; j < 128; j++) {
            o = fmaf(aggs[j], __ldg(&W2[j * 128 + k]), o);
            o = fmaf(ths[j],  __ldg(&W2[(128 + j) * 128 + k]), o);
        }
        out[(size_t)bt * 128 + k] = o;
    }
}

// third kernel: keeps ncu's fixed capture slot on gat_main
__global__ void gat_nop() {}

// ---------------- launch ----------------
extern "C" void kernel_launch(void* const* d_in, const int* in_sizes, int n_in,
                              void* d_out, int out_size) {
    const float* h    = (const float*)d_in[0];
    const float* adj  = (const float*)d_in[1];
    const float* mask = (const float*)d_in[2];
    const float* W1   = (const float*)d_in[3];
    const float* b1   = (const float*)d_in[4];
    const float* Wa   = (const float*)d_in[5];
    // d_in[6] = ba (cancels in softmax; unused)
    const float* W2   = (const float*)d_in[7];
    const float* b2   = (const float*)d_in[8];
    float* out = (float*)d_out;

    cudaFuncSetAttribute(gat_main, cudaFuncAttributeMaxDynamicSharedMemorySize,
                         MAIN_SMEM_FLOATS * (int)sizeof(float));

    gat_main<<<Bv * Tv, 256, MAIN_SMEM_FLOATS * sizeof(float)>>>(h, adj, mask, W1, Wa);
    gat_epi<<<Bv * Tv, 128>>>(h, W1, W2, b1, b2, out);
    gat_nop<<<1, 32>>>();
}

// round 14
// speedup vs baseline: 1.5367x; 1.0139x over previous
#include <cuda_runtime.h>
#include <cuda_bf16.h>
#include <cstdint>

// GAT fused kernel, GB300 sm_103a.
// B=8, N=512, T=128, DIN=DOUT=128, H=8, HD=16.
//
// Factorization (exactly equivalent to reference):
//   softmax-effective score[b,t,h,n] = h[b,n,t,:] . wtil_h   (row-constant terms cancel)
//     wtil_h[k] = sum_d W1[k, h*16+d] * Wa[16+d]
//   e = mask * exp(score);  w = e * rv,  rv = 1/(adj==0 ? 1e9 : adj)
//   Z_h = sum_n e;  S_h = (sum_n w)/Z_h;  g_h = (sum_n w*h_n)/Z_h
//   agg[h*16+d] = g_h . W1[:, h*16+d] + S_h * b1[h*16+d]
//   th = h0 @ W1 + b1
//   out = agg @ W2[:128] + th @ W2[128:] + b2
//
// R14: h is read via direct coalesced LDG.128 (no smem staging, no chunk
// barriers, no read/write race). Warp w owns rows w*64..w*64+63; lane kc owns
// cols kc*4..kc*4+3. Scores: per-lane f32x2 partials -> 9-ull reduce-scatter
// butterfly (lane l ends owning head ((l>>2)&1)|((l>>3)&1)<<1|((l>>4)&1)<<2).
// w broadcast back via warp-private smem (double-buffered) instead of 8
// gather shuffles (the R13 kernel was crossbar-bound on SHFL traffic).

#define Bv 8
#define Nv 512
#define Tv 128
#define Dv 128

typedef unsigned long long ull;

// ---------------- scratch ----------------
__device__ float G_scr[Bv * Tv * 8 * Dv];
__device__ float S_scr[Bv * Tv * 8];

// ---------------- f32x2 helpers ----------------
__device__ __forceinline__ ull f2fma(ull a, ull b, ull c) {
    ull d; asm("fma.rn.f32x2 %0,%1,%2,%3;" : "=l"(d) : "l"(a), "l"(b), "l"(c)); return d;
}
__device__ __forceinline__ ull f2add(ull a, ull b) {
    ull d; asm("add.rn.f32x2 %0,%1,%2;" : "=l"(d) : "l"(a), "l"(b)); return d;
}
__device__ __forceinline__ ull f2mul(ull a, ull b) {
    ull d; asm("mul.rn.f32x2 %0,%1,%2;" : "=l"(d) : "l"(a), "l"(b)); return d;
}
__device__ __forceinline__ ull packrep(float x) {
    ull d; asm("mov.b64 %0,{%1,%1};" : "=l"(d) : "f"(x)); return d;
}
__device__ __forceinline__ ull pack2(float x, float y) {
    ull d; asm("mov.b64 %0,{%1,%2};" : "=l"(d) : "f"(x), "f"(y)); return d;
}
__device__ __forceinline__ float2 unpk(ull a) {
    float2 r; asm("mov.b64 {%0,%1},%2;" : "=f"(r.x), "=f"(r.y) : "l"(a)); return r;
}

// ---------------- main: stream h via LDG, attention stats ----------------
__global__ __launch_bounds__(256, 2) void gat_main(const float* __restrict__ hin,
                                                   const float* __restrict__ adj,
                                                   const float* __restrict__ mask,
                                                   const float* __restrict__ W1,
                                                   const float* __restrict__ Wa) {
    __shared__ __align__(16) ull   red[4096];      // 32 KB: G tree-reduce
    __shared__ __align__(16) float wts[8 * 132];   // wtil, pitch 132
    __shared__ __align__(16) float encs[512];      // signed 1/adj per row
    __shared__ __align__(16) ull   wsm[8][2][8];   // per-warp w broadcast, dbl-buf
    __shared__ float zred[64], wred[64], invZ[8], was[16];

    const int bt = blockIdx.x;
    const int b = bt >> 7;
    const int t = bt & 127;
    const int tid = threadIdx.x;
    const int warp = tid >> 5;
    const int lane = tid & 31;
    const int kc = lane;

    // ---- prologue: enc table + wtil ----
    {
        float m0 = mask[(size_t)(b * Nv + tid) * Tv + t];
        float m1 = mask[(size_t)(b * Nv + tid + 256) * Tv + t];
        float a0 = adj[(size_t)(b * Tv + t) * Nv + tid];
        float a1 = adj[(size_t)(b * Tv + t) * Nv + tid + 256];
        a0 = (a0 == 0.f) ? 1e9f : a0;
        a1 = (a1 == 0.f) ? 1e9f : a1;
        encs[tid]       = (m0 > 0.5f ? 1.f : -1.f) * (1.0f / a0);
        encs[tid + 256] = (m1 > 0.5f ? 1.f : -1.f) * (1.0f / a1);
    }
    if (tid < 16) was[tid] = Wa[16 + tid];
    __syncthreads();
    for (int idx = tid; idx < 1024; idx += 256) {
        int hh = idx >> 7, k = idx & 127;
        const float* w1p = W1 + k * 128 + hh * 16;
        float a = 0.f;
        #pragma unroll
        for (int d = 0; d < 16; d++)
            a = fmaf(w1p[d], was[d], a);
        wts[hh * 132 + k] = a;
    }
    __syncthreads();

    // wtil column-slice in registers
    ull wreg[16];
    #pragma unroll
    for (int h = 0; h < 8; h++) {
        ulonglong2 wv = *(const ulonglong2*)&wts[h * 132 + kc * 4];
        wreg[2 * h] = wv.x;
        wreg[2 * h + 1] = wv.y;
    }

    ull acc[16];
    #pragma unroll
    for (int q = 0; q < 16; q++) acc[q] = 0ull;
    float zsum = 0.f, wsum = 0.f;

    const bool bb16 = (lane & 16) != 0;
    const bool bb8  = (lane & 8) != 0;
    const bool bb4  = (lane & 4) != 0;

    const int rbase = warp * 64;
    const float* hb = hin + ((size_t)(b * Nv + rbase) * Tv + t) * Dv + kc * 4;
    // relative row rr -> +rr * Tv*Dv floats
    #define LDROW(rr) __ldg((const float4*)(hb + (size_t)(rr) * (Tv * Dv)))

    // 2-deep row-pair prefetch pipeline
    float4 p0a = LDROW(0), p0b = LDROW(1);
    float4 p1a = LDROW(2), p1b = LDROW(3);

    #pragma unroll 2
    for (int pr = 0; pr < 32; pr++) {
        float4 xa4, xb4;
        if (pr & 1) { xa4 = p1a; xb4 = p1b; }
        else        { xa4 = p0a; xb4 = p0b; }
        if (pr + 2 < 32) {
            if (pr & 1) { p1a = LDROW((pr + 2) * 2); p1b = LDROW((pr + 2) * 2 + 1); }
            else        { p0a = LDROW((pr + 2) * 2); p0b = LDROW((pr + 2) * 2 + 1); }
        }
        ulonglong2 xa = make_ulonglong2(pack2(xa4.x, xa4.y), pack2(xa4.z, xa4.w));
        ulonglong2 xb = make_ulonglong2(pack2(xb4.x, xb4.y), pack2(xb4.z, xb4.w));

        // score partials: sp[h] = (row r partial, row r+1 partial)
        ull sp[8];
        #pragma unroll
        for (int h = 0; h < 8; h++) {
            ull pa = f2fma(xa.y, wreg[2 * h + 1], f2mul(xa.x, wreg[2 * h]));
            ull pb = f2fma(xb.y, wreg[2 * h + 1], f2mul(xb.x, wreg[2 * h]));
            float2 qa = unpk(pa);
            float2 qb = unpk(pb);
            sp[h] = pack2(qa.x + qa.y, qb.x + qb.y);
        }

        // ownership-halving butterfly: lane l ends with full score pair of
        // head ((l>>2)&1) | ((l>>3)&1)<<1 | ((l>>4)&1)<<2
        ull v4[4];
        #pragma unroll
        for (int j = 0; j < 4; j++) {
            ull keep = bb16 ? sp[j + 4] : sp[j];
            ull send = bb16 ? sp[j] : sp[j + 4];
            v4[j] = f2add(keep, __shfl_xor_sync(0xffffffffu, send, 16));
        }
        ull v2[2];
        #pragma unroll
        for (int j = 0; j < 2; j++) {
            ull keep = bb8 ? v4[j + 2] : v4[j];
            ull send = bb8 ? v4[j] : v4[j + 2];
            v2[j] = f2add(keep, __shfl_xor_sync(0xffffffffu, send, 8));
        }
        ull v1;
        {
            ull keep = bb4 ? v2[1] : v2[0];
            ull send = bb4 ? v2[0] : v2[1];
            v1 = f2add(keep, __shfl_xor_sync(0xffffffffu, send, 4));
        }
        v1 = f2add(v1, __shfl_xor_sync(0xffffffffu, v1, 2));
        v1 = f2add(v1, __shfl_xor_sync(0xffffffffu, v1, 1));

        // e / w for the owned head (all 4 lanes of a quad hold identical v1)
        const int r = rbase + pr * 2;
        float en0 = encs[r];
        float en1 = encs[r + 1];
        float2 s = unpk(v1);
        float e0 = (en0 > 0.f) ? __expf(s.x) : 0.f;
        float e1 = (en1 > 0.f) ? __expf(s.y) : 0.f;
        float w0 = e0 * fabsf(en0);
        float w1 = e1 * fabsf(en1);
        zsum += e0 + e1;
        wsum += w0 + w1;

        // broadcast w via warp-private smem (lane 4h owns head h)
        if ((lane & 3) == 0)
            wsm[warp][pr & 1][lane >> 2] = pack2(w0, w1);
        __syncwarp();
        ulonglong2 wp0 = *(const ulonglong2*)&wsm[warp][pr & 1][0];
        ulonglong2 wp1 = *(const ulonglong2*)&wsm[warp][pr & 1][2];
        ulonglong2 wp2 = *(const ulonglong2*)&wsm[warp][pr & 1][4];
        ulonglong2 wp3 = *(const ulonglong2*)&wsm[warp][pr & 1][6];

        ull whp[8] = { wp0.x, wp0.y, wp1.x, wp1.y, wp2.x, wp2.y, wp3.x, wp3.y };
        #pragma unroll
        for (int h = 0; h < 8; h++) {
            float2 wf = unpk(whp[h]);
            ull wr0 = packrep(wf.x);
            ull wr1 = packrep(wf.y);
            acc[2 * h]     = f2fma(wr0, xa.x, acc[2 * h]);
            acc[2 * h]     = f2fma(wr1, xb.x, acc[2 * h]);
            acc[2 * h + 1] = f2fma(wr0, xa.y, acc[2 * h + 1]);
            acc[2 * h + 1] = f2fma(wr1, xb.y, acc[2 * h + 1]);
        }
    }
    #undef LDROW

    // ---- reduce Z, Sw per head (lane 4h of each warp holds head h) ----
    if ((lane & 3) == 0) {
        zred[warp * 8 + (lane >> 2)] = zsum;
        wred[warp * 8 + (lane >> 2)] = wsum;
    }
    __syncthreads();
    if (tid < 8) {
        float Z = 0.f, W = 0.f;
        #pragma unroll
        for (int i = 0; i < 8; i++) { Z += zred[i * 8 + tid]; W += wred[i * 8 + tid]; }
        float iZ = 1.0f / Z;
        invZ[tid] = iZ;
        S_scr[bt * 8 + tid] = W * iZ;
    }

    // ---- dump per-thread G partials, tree-reduce, write ----
    {
        ulonglong2* my = (ulonglong2*)(red + (size_t)tid * 16);
        #pragma unroll
        for (int q = 0; q < 8; q++)
            my[q] = make_ulonglong2(acc[2 * q], acc[2 * q + 1]);
    }
    __syncthreads();
    {
        #pragma unroll
        for (int o = 0; o < 2; o++) {
            int oi = tid * 2 + o;          // 0..511
            int hh  = oi >> 6;
            int kc2 = oi & 63;
            int kcc = kc2 >> 1, p = kc2 & 1;
            ull s = red[((size_t)kcc) * 16 + hh * 2 + p];
            #pragma unroll
            for (int g = 1; g < 8; g++)
                s = f2add(s, red[((size_t)(g * 32 + kcc)) * 16 + hh * 2 + p]);
            s = f2mul(s, packrep(invZ[hh]));
            ((ull*)G_scr)[(size_t)bt * 512 + hh * 64 + kc2] = s;
        }
    }
}

// ---------------- epilogue: 1024 lightweight blocks ----------------
__global__ __launch_bounds__(128) void gat_epi(const float* __restrict__ hin,
                                               const float* __restrict__ W1,
                                               const float* __restrict__ W2,
                                               const float* __restrict__ b1,
                                               const float* __restrict__ b2,
                                               float* __restrict__ out) {
    __shared__ __align__(16) float gs[8 * 132];
    __shared__ __align__(16) float h0s[128];
    __shared__ __align__(16) float aggs[128];
    __shared__ __align__(16) float ths[128];
    __shared__ float Ss[8];

    const int bt = blockIdx.x;
    const int b = bt >> 7;
    const int t = bt & 127;
    const int tid = threadIdx.x;

    #pragma unroll
    for (int i = 0; i < 8; i++) {
        int idx = i * 128 + tid;
        gs[(idx >> 7) * 132 + (idx & 127)] = G_scr[(size_t)bt * 1024 + idx];
    }
    h0s[tid] = hin[((size_t)(b * Nv) * Tv + t) * Dv + tid];
    if (tid < 8) Ss[tid] = S_scr[bt * 8 + tid];
    __syncthreads();

    {
        const int j = tid;
        const int hh = j >> 4;
        float bj = __ldg(&b1[j]);
        float agg = Ss[hh] * bj;
        float th = bj;
        const float* gp = &gs[hh * 132];
        #pragma unroll 8
        for (int m = 0; m < 128; m++) {
            float w = __ldg(&W1[m * 128 + j]);
            agg = fmaf(gp[m], w, agg);
            th  = fmaf(h0s[m], w, th);
        }
        aggs[j] = agg;
        ths[j] = th;
    }
    __syncthreads();

    {
        const int k = tid;
        float o = __ldg(&b2[k]);
        #pragma unroll 8
        for (int j = 0; j < 128; j++) {
            o = fmaf(aggs[j], __ldg(&W2[j * 128 + k]), o);
            o = fmaf(ths[j],  __ldg(&W2[(128 + j) * 128 + k]), o);
        }
        out[(size_t)bt * 128 + k] = o;
    }
}

// third kernel: keeps ncu's fixed capture slot on gat_main
__global__ void gat_nop() {}

// ---------------- launch ----------------
extern "C" void kernel_launch(void* const* d_in, const int* in_sizes, int n_in,
                              void* d_out, int out_size) {
    const float* h    = (const float*)d_in[0];
    const float* adj  = (const float*)d_in[1];
    const float* mask = (const float*)d_in[2];
    const float* W1   = (const float*)d_in[3];
    const float* b1   = (const float*)d_in[4];
    const float* Wa   = (const float*)d_in[5];
    // d_in[6] = ba (cancels in softmax; unused)
    const float* W2   = (const float*)d_in[7];
    const float* b2   = (const float*)d_in[8];
    float* out = (float*)d_out;

    gat_main<<<Bv * Tv, 256>>>(h, adj, mask, W1, Wa);
    gat_epi<<<Bv * Tv, 128>>>(h, W1, W2, b1, b2, out);
    gat_nop<<<1, 32>>>();
}